// round 14
// baseline (speedup 1.0000x reference)
#include <cuda_runtime.h>
#include <cuda_fp16.h>
#include <math.h>
#include <stdint.h>

#define BZ 2
#define CC 128
#define NN 2304
#define WIMG 48
#define ROWS 32         // n-rows per block
#define MC 128          // m-chunk width
#define NCH 9           // chunks per m-half (9*128 = 1152)
#define MHALF 1152
#define BPAD 68         // u32 row stride staged A/B (mod 32 == 4 -> frag reads conflict-free)
#define SSTR 129        // Ss row stride floats (mod 32 == 1 -> binning reads conflict-free)

// ---------------- scratch ----------------
__device__ __half g_Qh[BZ * NN * CC];               // img1 -> [b][n][c] half
__device__ __half g_Th[BZ * NN * CC];               // img2 -> [b][p][c] half
__device__ __half g_Dh[BZ * NN * CC];               // sampled db [b][n][c] half
__device__ float g_histP[(size_t)BZ * 2 * NN * 50]; // per-mhalf hists [b][mh][n][slot]
__device__ float g_part[576];
__device__ unsigned g_ctr = 0;

// ---------------- kernel 1: transpose + cvt half ----------
__global__ void k_prep(const float* __restrict__ img1, const float* __restrict__ img2) {
    __shared__ float tile[32][33];
    int img = blockIdx.z & 1;
    int b   = blockIdx.z >> 1;
    const float* in = (img == 0 ? img1 : img2) + (size_t)b * CC * NN;
    __half* out     = (img == 0 ? g_Qh : g_Th) + (size_t)b * NN * CC;

    int p0 = blockIdx.x * 32;
    int c0 = blockIdx.y * 32;
    int tx = threadIdx.x, ty = threadIdx.y;

#pragma unroll
    for (int j = 0; j < 4; j++)
        tile[ty + j * 8][tx] = in[(size_t)(c0 + ty + j * 8) * NN + p0 + tx];
    __syncthreads();
#pragma unroll
    for (int j = 0; j < 4; j++)
        out[(size_t)(p0 + ty + j * 8) * CC + c0 + tx] =
            __float2half(tile[tx][ty + j * 8]);
}

// ---------------- kernel 2: grid_sample ----------------
__global__ void k_gridsample(const float* __restrict__ grid) {
    int w    = threadIdx.x >> 5;
    int lane = threadIdx.x & 31;
    int n = blockIdx.x * 8 + w;
    int b = blockIdx.y;

    float gx = grid[((size_t)b * NN + n) * 2 + 0];
    float gy = grid[((size_t)b * NN + n) * 2 + 1];
    float ix = fmaf(gx, 24.0f, 23.5f);
    float iy = fmaf(gy, 24.0f, 23.5f);
    float x0f = floorf(ix), y0f = floorf(iy);
    float wx = ix - x0f, wy = iy - y0f;
    int x0 = (int)x0f, y0 = (int)y0f;
    int x1 = x0 + 1,  y1 = y0 + 1;

    bool vx0 = (x0 >= 0) & (x0 < WIMG);
    bool vx1 = (x1 >= 0) & (x1 < WIMG);
    bool vy0 = (y0 >= 0) & (y0 < WIMG);
    bool vy1 = (y1 >= 0) & (y1 < WIMG);

    float w00 = (vx0 & vy0) ? (1.f - wx) * (1.f - wy) : 0.f;
    float w10 = (vx1 & vy0) ? wx * (1.f - wy)         : 0.f;
    float w01 = (vx0 & vy1) ? (1.f - wx) * wy         : 0.f;
    float w11 = (vx1 & vy1) ? wx * wy                 : 0.f;

    int cx0 = min(max(x0, 0), WIMG - 1), cx1 = min(max(x1, 0), WIMG - 1);
    int cy0 = min(max(y0, 0), WIMG - 1), cy1 = min(max(y1, 0), WIMG - 1);

    const __half* T = g_Th + (size_t)b * NN * CC;
    int p00 = cy0 * WIMG + cx0, p10 = cy0 * WIMG + cx1;
    int p01 = cy1 * WIMG + cx0, p11 = cy1 * WIMG + cx1;

    uint2 v00 = ((const uint2*)(T + (size_t)p00 * CC))[lane];
    uint2 v10 = ((const uint2*)(T + (size_t)p10 * CC))[lane];
    uint2 v01 = ((const uint2*)(T + (size_t)p01 * CC))[lane];
    uint2 v11 = ((const uint2*)(T + (size_t)p11 * CC))[lane];

    float r[4];
#pragma unroll
    for (int h = 0; h < 2; h++) {
        float2 f00 = __half22float2(((__half2*)&v00)[h]);
        float2 f10 = __half22float2(((__half2*)&v10)[h]);
        float2 f01 = __half22float2(((__half2*)&v01)[h]);
        float2 f11 = __half22float2(((__half2*)&v11)[h]);
        r[2 * h + 0] = w00 * f00.x + w10 * f10.x + w01 * f01.x + w11 * f11.x;
        r[2 * h + 1] = w00 * f00.y + w10 * f10.y + w01 * f01.y + w11 * f11.y;
    }
    uint2 o;
    ((__half2*)&o)[0] = __floats2half2_rn(r[0], r[1]);
    ((__half2*)&o)[1] = __floats2half2_rn(r[2], r[3]);
    ((uint2*)(g_Dh + ((size_t)b * NN + n) * CC))[lane] = o;
}

// ---------------- fp16 MMA ----------------
__device__ __forceinline__ void mma_f16(float* d, const uint32_t* a, const uint32_t* bb) {
    asm volatile(
        "mma.sync.aligned.m16n8k16.row.col.f32.f16.f16.f32 "
        "{%0,%1,%2,%3}, {%4,%5,%6,%7}, {%8,%9}, {%0,%1,%2,%3};"
        : "+f"(d[0]), "+f"(d[1]), "+f"(d[2]), "+f"(d[3])
        : "r"(a[0]), "r"(a[1]), "r"(a[2]), "r"(a[3]), "r"(bb[0]), "r"(bb[1]));
}

// ---------------- kernel 3: GEMM + binning over one m-half (288 blocks, occ 2) ----
#define SM_SS   0                          // 32*129 = 4128
#define SM_HN   (SM_SS + ROWS * SSTR)      // 26*256 = 6656
#define SM_HR   (SM_HN + 26 * 256)         // 6656
#define SM_A    (SM_HR + 26 * 256)         // 32*68 u32 = 2176
#define SM_B    (SM_A + ROWS * BPAD)       // 128*68 u32 = 8704
#define SM_TOT  (SM_B + MC * BPAD)         // 28320 floats = 113280 B

__global__ void __launch_bounds__(256, 2) k_main() {
    extern __shared__ float smf[];
    float*    Ss  = smf + SM_SS;
    float*    hN  = smf + SM_HN;
    float*    hR  = smf + SM_HR;
    uint32_t* As2 = (uint32_t*)(smf + SM_A);
    uint32_t* Bs2 = (uint32_t*)(smf + SM_B);

    const int t  = threadIdx.x;
    const int w  = t >> 5;
    const int ln = t & 31;
    const int g  = ln >> 2;
    const int tg = ln & 3;
    const int nt = blockIdx.x;
    const int mh = blockIdx.y;
    const int b  = blockIdx.z;
    const int n0 = nt * ROWS;
    const int mbase = mh * MHALF;

    // zero private hist columns
#pragma unroll
    for (int c = 0; c < 26; c++) { hN[c * 256 + t] = 0.f; hR[c * 256 + t] = 0.f; }

    // stage A (32 rows x 128 c): 512 uint4, 2 per thread
    const __half* Qh = g_Qh + ((size_t)b * NN + n0) * CC;
#pragma unroll
    for (int i = 0; i < 2; i++) {
        int idx = t + i * 256;
        int row = idx >> 4, c4 = idx & 15;
        uint4 v = ((const uint4*)(Qh + (size_t)row * CC))[c4];
        *(uint4*)&As2[row * BPAD + c4 * 4] = v;
    }

    // binning identities: lane = row
    const int ng = n0 + ln;
    const int rn = ng / WIMG;
    const int cn = ng - rn * WIMG;

    const __half* Dh = g_Dh + (size_t)(b * NN + mbase) * CC;

    // preload B chunk 0: 2048 uint4, 8 per thread
#pragma unroll
    for (int i = 0; i < 8; i++) {
        int idx = t + i * 256;
        int m = idx >> 4, c4 = idx & 15;
        uint4 v = ((const uint4*)(Dh + (size_t)m * CC))[c4];
        *(uint4*)&Bs2[m * BPAD + c4 * 4] = v;
    }
    __syncthreads();

    for (int mc = 0; mc < NCH; mc++) {
        const int m0 = mc * MC;

        // ---- GEMM: warp w covers m-cols [w*16, w*16+16) ----
        float acc[2][2][4];
#pragma unroll
        for (int i = 0; i < 2; i++)
#pragma unroll
            for (int j = 0; j < 2; j++)
#pragma unroll
                for (int k = 0; k < 4; k++) acc[i][j][k] = 0.f;

#pragma unroll
        for (int kk = 0; kk < 8; kk++) {
            int kb = kk * 8 + tg;
            uint32_t af[2][4];
#pragma unroll
            for (int rt = 0; rt < 2; rt++) {
                int nb = rt * 16 + g;
                af[rt][0] = As2[nb * BPAD + kb];
                af[rt][1] = As2[(nb + 8) * BPAD + kb];
                af[rt][2] = As2[nb * BPAD + kb + 4];
                af[rt][3] = As2[(nb + 8) * BPAD + kb + 4];
            }
#pragma unroll
            for (int ct = 0; ct < 2; ct++) {
                int mb = w * 16 + ct * 8 + g;
                uint32_t bf[2];
                bf[0] = Bs2[mb * BPAD + kb];
                bf[1] = Bs2[mb * BPAD + kb + 4];
#pragma unroll
                for (int rt = 0; rt < 2; rt++)
                    mma_f16(acc[rt][ct], af[rt], bf);
            }
        }

        // fragments -> Ss (scalar stores: SSTR odd)
#pragma unroll
        for (int rt = 0; rt < 2; rt++) {
            int row = rt * 16 + g;
#pragma unroll
            for (int ct = 0; ct < 2; ct++) {
                int col = w * 16 + ct * 8 + tg * 2;
                Ss[row * SSTR + col]           = acc[rt][ct][0];
                Ss[row * SSTR + col + 1]       = acc[rt][ct][1];
                Ss[(row + 8) * SSTR + col]     = acc[rt][ct][2];
                Ss[(row + 8) * SSTR + col + 1] = acc[rt][ct][3];
            }
        }
        __syncthreads();

        // ---- stage next B chunk (overlaps binning) ----
        if (mc + 1 < NCH) {
            const __half* Dn = Dh + (size_t)(m0 + MC) * CC;
#pragma unroll
            for (int i = 0; i < 8; i++) {
                int idx = t + i * 256;
                int m = idx >> 4, c4 = idx & 15;
                uint4 v = ((const uint4*)(Dn + (size_t)m * CC))[c4];
                *(uint4*)&Bs2[m * BPAD + c4 * 4] = v;
            }
        }

        // ---- binning: row = lane, warp w covers m = w + 8j ----
        {
            float* hNc = hN + t;
            float* hRc = hR + t;
            const int mgb = mbase + m0 + w;
#pragma unroll
            for (int j = 0; j < 16; j++) {
                int ml = w + 8 * j;
                float s = Ss[ln * SSTR + ml];
                int mg = mgb + 8 * j;
                int rm = mg / WIMG;
                int cm = mg - rm * WIMG;
                bool lab = (abs(rm - rn) <= 4) && (abs(cm - cn) <= 4);
                float tq = fmaf(s, -12.f, 12.f);
                tq = fminf(fmaxf(tq, 0.f), 24.f);
                float cf = floorf(tq);
                int c0 = (int)cf;
                float whi = tq - cf;
                float wlo = 1.f - whi;
                hNc[c0 * 256]       += wlo;
                hNc[c0 * 256 + 256] += whi;
                if (__any_sync(0xffffffffu, lab)) {
                    if (lab) {
                        hRc[c0 * 256]       += wlo;
                        hRc[c0 * 256 + 256] += whi;
                    }
                }
            }
        }
        __syncthreads();
    }

    // ---- flush: 50 slots x 32 rows -> g_histP[b][mh][n][slot] (row-major) ----
    float* outp = g_histP + ((size_t)((b * 2 + mh) * NN + n0)) * 50;
#pragma unroll
    for (int kk = 0; kk < 7; kk++) {
        int idx = t + kk * 256;            // 0..1599 used
        if (idx < 1600) {
            int s50 = idx >> 5;            // 0..49
            int r   = idx & 31;
            float* hh = (s50 < 25) ? (hN + s50 * 256) : (hR + (s50 - 25) * 256);
            float v = 0.f;
#pragma unroll
            for (int u = 0; u < 8; u++) v += hh[u * 32 + r];
            outp[(size_t)r * 50 + s50] = v;
        }
    }
}

// ---------------- kernel 4: AP + loss, warp-per-row, coalesced row-major hists ----
__global__ void __launch_bounds__(256) k_fin(const float* __restrict__ rel,
                                             float* __restrict__ out) {
    const int wib  = threadIdx.x >> 5;
    const int lane = threadIdx.x & 31;
    const int row  = blockIdx.x * 8 + wib;     // 0..4607
    const int b = row / NN;
    const int n = row - b * NN;

    const float* P0 = g_histP + ((size_t)((b * 2 + 0) * NN + n)) * 50;
    const float* P1 = g_histP + ((size_t)((b * 2 + 1) * NN + n)) * 50;

    float nb = 0.f, rv = 0.f;
    if (lane < 25) {
        nb = P0[lane]      + P1[lane];
        rv = P0[25 + lane] + P1[25 + lane];
    }

    // inclusive scans over lanes (bins)
    float cumn = nb, cumr = rv;
#pragma unroll
    for (int o = 1; o < 32; o <<= 1) {
        float a = __shfl_up_sync(0xffffffffu, cumn, o);
        float c = __shfl_up_sync(0xffffffffu, cumr, o);
        if (lane >= o) { cumn += a; cumr += c; }
    }
    float prec = cumr / (1e-16f + cumn);
    float term = prec * rv;                    // lanes >= 25 contribute 0
    float sr   = rv;
#pragma unroll
    for (int o = 16; o > 0; o >>= 1) {
        term += __shfl_down_sync(0xffffffffu, term, o);
        sr   += __shfl_down_sync(0xffffffffu, sr, o);
    }

    __shared__ float red[8];
    if (lane == 0) {
        float ap = term / sr;
        float rl = rel[(size_t)b * NN + n];
        red[wib] = 1.f - (ap * rl + 0.5f * (1.f - rl));
    }
    __syncthreads();

    __shared__ bool s_last;
    if (threadIdx.x == 0) {
        float bs = 0.f;
#pragma unroll
        for (int i = 0; i < 8; i++) bs += red[i];
        g_part[blockIdx.x] = bs;
        __threadfence();
        unsigned old = atomicAdd(&g_ctr, 1u);
        s_last = (old == 575u);
    }
    __syncthreads();

    if (s_last) {
        __threadfence();
        float v = 0.f;
#pragma unroll
        for (int i = 0; i < 3; i++) {
            int idx = threadIdx.x + i * 256;
            if (idx < 576) v += g_part[idx];
        }
        __shared__ float rr[256];
        rr[threadIdx.x] = v;
        __syncthreads();
#pragma unroll
        for (int s = 128; s > 0; s >>= 1) {
            if (threadIdx.x < s) rr[threadIdx.x] += rr[threadIdx.x + s];
            __syncthreads();
        }
        if (threadIdx.x == 0) {
            out[0] = rr[0] * (1.0f / 4608.0f);
            g_ctr = 0u;
        }
    }
}

// ---------------- launch ----------------
extern "C" void kernel_launch(void* const* d_in, const int* in_sizes, int n_in,
                              void* d_out, int out_size) {
    const float* img1 = (const float*)d_in[0];
    const float* img2 = (const float*)d_in[1];
    const float* rel  = (const float*)d_in[2];
    const float* grid = (const float*)d_in[3];

    cudaFuncSetAttribute(k_main, cudaFuncAttributeMaxDynamicSharedMemorySize,
                         SM_TOT * (int)sizeof(float));

    k_prep<<<dim3(72, 4, 4), dim3(32, 8)>>>(img1, img2);
    k_gridsample<<<dim3(288, 2), 256>>>(grid);
    k_main<<<dim3(72, 2, 2), 256, SM_TOT * (int)sizeof(float)>>>();
    k_fin<<<576, 256>>>(rel, (float*)d_out);
}

// round 15
// speedup vs baseline: 1.1085x; 1.1085x over previous
#include <cuda_runtime.h>
#include <cuda_fp16.h>
#include <math.h>
#include <stdint.h>

#define BZ 2
#define CC 128
#define NN 2304
#define WIMG 48
#define ROWS 32         // n-rows per block
#define MC 128          // m-chunk width
#define NCH 9           // chunks per m-half (9*128 = 1152)
#define MHALF 1152
#define BPAD 68         // u32 row stride staged A/B (mod 32 == 4 -> frag reads conflict-free)
#define SSTR 129        // Ss row stride floats (mod 32 == 1 -> binning reads conflict-free)

// ---------------- scratch ----------------
__device__ __half g_Qh[BZ * NN * CC];               // img1 -> [b][n][c] half
__device__ __half g_Th[BZ * NN * CC];               // img2 -> [b][p][c] half
__device__ __half g_Dh[BZ * NN * CC];               // sampled db [b][n][c] half
__device__ float g_histP[(size_t)BZ * 2 * NN * 50]; // per-mhalf hists [b][mh][n][slot]
__device__ float g_part[576];
__device__ unsigned g_ctr = 0;

// ---------------- kernel 1: transpose + cvt half ----------
__global__ void k_prep(const float* __restrict__ img1, const float* __restrict__ img2) {
    __shared__ float tile[32][33];
    int img = blockIdx.z & 1;
    int b   = blockIdx.z >> 1;
    const float* in = (img == 0 ? img1 : img2) + (size_t)b * CC * NN;
    __half* out     = (img == 0 ? g_Qh : g_Th) + (size_t)b * NN * CC;

    int p0 = blockIdx.x * 32;
    int c0 = blockIdx.y * 32;
    int tx = threadIdx.x, ty = threadIdx.y;

#pragma unroll
    for (int j = 0; j < 4; j++)
        tile[ty + j * 8][tx] = in[(size_t)(c0 + ty + j * 8) * NN + p0 + tx];
    __syncthreads();
#pragma unroll
    for (int j = 0; j < 4; j++)
        out[(size_t)(p0 + ty + j * 8) * CC + c0 + tx] =
            __float2half(tile[tx][ty + j * 8]);
}

// ---------------- kernel 2: grid_sample ----------------
__global__ void k_gridsample(const float* __restrict__ grid) {
    int w    = threadIdx.x >> 5;
    int lane = threadIdx.x & 31;
    int n = blockIdx.x * 8 + w;
    int b = blockIdx.y;

    float gx = grid[((size_t)b * NN + n) * 2 + 0];
    float gy = grid[((size_t)b * NN + n) * 2 + 1];
    float ix = fmaf(gx, 24.0f, 23.5f);
    float iy = fmaf(gy, 24.0f, 23.5f);
    float x0f = floorf(ix), y0f = floorf(iy);
    float wx = ix - x0f, wy = iy - y0f;
    int x0 = (int)x0f, y0 = (int)y0f;
    int x1 = x0 + 1,  y1 = y0 + 1;

    bool vx0 = (x0 >= 0) & (x0 < WIMG);
    bool vx1 = (x1 >= 0) & (x1 < WIMG);
    bool vy0 = (y0 >= 0) & (y0 < WIMG);
    bool vy1 = (y1 >= 0) & (y1 < WIMG);

    float w00 = (vx0 & vy0) ? (1.f - wx) * (1.f - wy) : 0.f;
    float w10 = (vx1 & vy0) ? wx * (1.f - wy)         : 0.f;
    float w01 = (vx0 & vy1) ? (1.f - wx) * wy         : 0.f;
    float w11 = (vx1 & vy1) ? wx * wy                 : 0.f;

    int cx0 = min(max(x0, 0), WIMG - 1), cx1 = min(max(x1, 0), WIMG - 1);
    int cy0 = min(max(y0, 0), WIMG - 1), cy1 = min(max(y1, 0), WIMG - 1);

    const __half* T = g_Th + (size_t)b * NN * CC;
    int p00 = cy0 * WIMG + cx0, p10 = cy0 * WIMG + cx1;
    int p01 = cy1 * WIMG + cx0, p11 = cy1 * WIMG + cx1;

    uint2 v00 = ((const uint2*)(T + (size_t)p00 * CC))[lane];
    uint2 v10 = ((const uint2*)(T + (size_t)p10 * CC))[lane];
    uint2 v01 = ((const uint2*)(T + (size_t)p01 * CC))[lane];
    uint2 v11 = ((const uint2*)(T + (size_t)p11 * CC))[lane];

    float r[4];
#pragma unroll
    for (int h = 0; h < 2; h++) {
        float2 f00 = __half22float2(((__half2*)&v00)[h]);
        float2 f10 = __half22float2(((__half2*)&v10)[h]);
        float2 f01 = __half22float2(((__half2*)&v01)[h]);
        float2 f11 = __half22float2(((__half2*)&v11)[h]);
        r[2 * h + 0] = w00 * f00.x + w10 * f10.x + w01 * f01.x + w11 * f11.x;
        r[2 * h + 1] = w00 * f00.y + w10 * f10.y + w01 * f01.y + w11 * f11.y;
    }
    uint2 o;
    ((__half2*)&o)[0] = __floats2half2_rn(r[0], r[1]);
    ((__half2*)&o)[1] = __floats2half2_rn(r[2], r[3]);
    ((uint2*)(g_Dh + ((size_t)b * NN + n) * CC))[lane] = o;
}

// ---------------- fp16 MMA ----------------
__device__ __forceinline__ void mma_f16(float* d, const uint32_t* a, const uint32_t* bb) {
    asm volatile(
        "mma.sync.aligned.m16n8k16.row.col.f32.f16.f16.f32 "
        "{%0,%1,%2,%3}, {%4,%5,%6,%7}, {%8,%9}, {%0,%1,%2,%3};"
        : "+f"(d[0]), "+f"(d[1]), "+f"(d[2]), "+f"(d[3])
        : "r"(a[0]), "r"(a[1]), "r"(a[2]), "r"(a[3]), "r"(bb[0]), "r"(bb[1]));
}

// ---------------- kernel 3: GEMM + binning over one m-half (288 blocks, occ 2) ----
#define SM_SS   0                          // 32*129 = 4128
#define SM_HN   (SM_SS + ROWS * SSTR)      // 26*256 = 6656
#define SM_HR   (SM_HN + 26 * 256)         // 6656
#define SM_A    (SM_HR + 26 * 256)         // 32*68 u32 = 2176
#define SM_B    (SM_A + ROWS * BPAD)       // 128*68 u32 = 8704
#define SM_TOT  (SM_B + MC * BPAD)         // 28320 floats = 113280 B

__global__ void __launch_bounds__(256, 2) k_main() {
    extern __shared__ float smf[];
    float*    Ss  = smf + SM_SS;
    float*    hN  = smf + SM_HN;
    float*    hR  = smf + SM_HR;
    uint32_t* As2 = (uint32_t*)(smf + SM_A);
    uint32_t* Bs2 = (uint32_t*)(smf + SM_B);

    const int t  = threadIdx.x;
    const int w  = t >> 5;
    const int ln = t & 31;
    const int g  = ln >> 2;
    const int tg = ln & 3;
    const int nt = blockIdx.x;
    const int mh = blockIdx.y;
    const int b  = blockIdx.z;
    const int n0 = nt * ROWS;
    const int mbase = mh * MHALF;

    // zero private hist columns
#pragma unroll
    for (int c = 0; c < 26; c++) { hN[c * 256 + t] = 0.f; hR[c * 256 + t] = 0.f; }

    // stage A (32 rows x 128 c): 512 uint4, 2 per thread
    const __half* Qh = g_Qh + ((size_t)b * NN + n0) * CC;
#pragma unroll
    for (int i = 0; i < 2; i++) {
        int idx = t + i * 256;
        int row = idx >> 4, c4 = idx & 15;
        uint4 v = ((const uint4*)(Qh + (size_t)row * CC))[c4];
        *(uint4*)&As2[row * BPAD + c4 * 4] = v;
    }

    // binning identities: lane = row
    const int ng = n0 + ln;
    const int rn = ng / WIMG;
    const int cn = ng - rn * WIMG;

    const __half* Dh = g_Dh + (size_t)(b * NN + mbase) * CC;

    // preload B chunk 0: 2048 uint4, 8 per thread
#pragma unroll
    for (int i = 0; i < 8; i++) {
        int idx = t + i * 256;
        int m = idx >> 4, c4 = idx & 15;
        uint4 v = ((const uint4*)(Dh + (size_t)m * CC))[c4];
        *(uint4*)&Bs2[m * BPAD + c4 * 4] = v;
    }
    __syncthreads();

    // ---- cache ALL A fragments in registers (A is chunk-invariant) ----
    uint32_t afr[8][2][4];
#pragma unroll
    for (int kk = 0; kk < 8; kk++) {
        int kb = kk * 8 + tg;
#pragma unroll
        for (int rt = 0; rt < 2; rt++) {
            int nb = rt * 16 + g;
            afr[kk][rt][0] = As2[nb * BPAD + kb];
            afr[kk][rt][1] = As2[(nb + 8) * BPAD + kb];
            afr[kk][rt][2] = As2[nb * BPAD + kb + 4];
            afr[kk][rt][3] = As2[(nb + 8) * BPAD + kb + 4];
        }
    }

    for (int mc = 0; mc < NCH; mc++) {
        const int m0 = mc * MC;

        // ---- GEMM: warp w covers m-cols [w*16, w*16+16) ----
        float acc[2][2][4];
#pragma unroll
        for (int i = 0; i < 2; i++)
#pragma unroll
            for (int j = 0; j < 2; j++)
#pragma unroll
                for (int k = 0; k < 4; k++) acc[i][j][k] = 0.f;

#pragma unroll
        for (int kk = 0; kk < 8; kk++) {
            int kb = kk * 8 + tg;
#pragma unroll
            for (int ct = 0; ct < 2; ct++) {
                int mb = w * 16 + ct * 8 + g;
                uint32_t bf[2];
                bf[0] = Bs2[mb * BPAD + kb];
                bf[1] = Bs2[mb * BPAD + kb + 4];
#pragma unroll
                for (int rt = 0; rt < 2; rt++)
                    mma_f16(acc[rt][ct], afr[kk][rt], bf);
            }
        }

        // fragments -> Ss (scalar stores: SSTR odd)
#pragma unroll
        for (int rt = 0; rt < 2; rt++) {
            int row = rt * 16 + g;
#pragma unroll
            for (int ct = 0; ct < 2; ct++) {
                int col = w * 16 + ct * 8 + tg * 2;
                Ss[row * SSTR + col]           = acc[rt][ct][0];
                Ss[row * SSTR + col + 1]       = acc[rt][ct][1];
                Ss[(row + 8) * SSTR + col]     = acc[rt][ct][2];
                Ss[(row + 8) * SSTR + col + 1] = acc[rt][ct][3];
            }
        }
        __syncthreads();

        // ---- stage next B chunk (overlaps binning) ----
        if (mc + 1 < NCH) {
            const __half* Dn = Dh + (size_t)(m0 + MC) * CC;
#pragma unroll
            for (int i = 0; i < 8; i++) {
                int idx = t + i * 256;
                int m = idx >> 4, c4 = idx & 15;
                uint4 v = ((const uint4*)(Dn + (size_t)m * CC))[c4];
                *(uint4*)&Bs2[m * BPAD + c4 * 4] = v;
            }
        }

        // ---- binning: row = lane, warp w covers m = w + 8j ----
        {
            float* hNc = hN + t;
            float* hRc = hR + t;
            const int mgb = mbase + m0 + w;
#pragma unroll
            for (int j = 0; j < 16; j++) {
                int ml = w + 8 * j;
                float s = Ss[ln * SSTR + ml];
                int mg = mgb + 8 * j;
                int rm = mg / WIMG;
                int cm = mg - rm * WIMG;
                bool lab = (abs(rm - rn) <= 4) && (abs(cm - cn) <= 4);
                float tq = fmaf(s, -12.f, 12.f);
                tq = fminf(fmaxf(tq, 0.f), 24.f);
                float cf = floorf(tq);
                int c0 = (int)cf;
                float whi = tq - cf;
                float wlo = 1.f - whi;
                hNc[c0 * 256]       += wlo;
                hNc[c0 * 256 + 256] += whi;
                if (__any_sync(0xffffffffu, lab)) {
                    if (lab) {
                        hRc[c0 * 256]       += wlo;
                        hRc[c0 * 256 + 256] += whi;
                    }
                }
            }
        }
        __syncthreads();
    }

    // ---- flush: 50 slots x 32 rows -> g_histP[b][mh][n][slot] (row-major) ----
    float* outp = g_histP + ((size_t)((b * 2 + mh) * NN + n0)) * 50;
#pragma unroll
    for (int kk = 0; kk < 7; kk++) {
        int idx = t + kk * 256;            // 0..1599 used
        if (idx < 1600) {
            int s50 = idx >> 5;            // 0..49
            int r   = idx & 31;
            float* hh = (s50 < 25) ? (hN + s50 * 256) : (hR + (s50 - 25) * 256);
            float v = 0.f;
#pragma unroll
            for (int u = 0; u < 8; u++) v += hh[u * 32 + r];
            outp[(size_t)r * 50 + s50] = v;
        }
    }
}

// ---------------- kernel 4: AP + loss, warp-per-row, coalesced row-major hists ----
__global__ void __launch_bounds__(256) k_fin(const float* __restrict__ rel,
                                             float* __restrict__ out) {
    const int wib  = threadIdx.x >> 5;
    const int lane = threadIdx.x & 31;
    const int row  = blockIdx.x * 8 + wib;     // 0..4607
    const int b = row / NN;
    const int n = row - b * NN;

    const float* P0 = g_histP + ((size_t)((b * 2 + 0) * NN + n)) * 50;
    const float* P1 = g_histP + ((size_t)((b * 2 + 1) * NN + n)) * 50;

    float nb = 0.f, rv = 0.f;
    if (lane < 25) {
        nb = P0[lane]      + P1[lane];
        rv = P0[25 + lane] + P1[25 + lane];
    }

    // inclusive scans over lanes (bins)
    float cumn = nb, cumr = rv;
#pragma unroll
    for (int o = 1; o < 32; o <<= 1) {
        float a = __shfl_up_sync(0xffffffffu, cumn, o);
        float c = __shfl_up_sync(0xffffffffu, cumr, o);
        if (lane >= o) { cumn += a; cumr += c; }
    }
    float prec = cumr / (1e-16f + cumn);
    float term = prec * rv;                    // lanes >= 25 contribute 0
    float sr   = rv;
#pragma unroll
    for (int o = 16; o > 0; o >>= 1) {
        term += __shfl_down_sync(0xffffffffu, term, o);
        sr   += __shfl_down_sync(0xffffffffu, sr, o);
    }

    __shared__ float red[8];
    if (lane == 0) {
        float ap = term / sr;
        float rl = rel[(size_t)b * NN + n];
        red[wib] = 1.f - (ap * rl + 0.5f * (1.f - rl));
    }
    __syncthreads();

    __shared__ bool s_last;
    if (threadIdx.x == 0) {
        float bs = 0.f;
#pragma unroll
        for (int i = 0; i < 8; i++) bs += red[i];
        g_part[blockIdx.x] = bs;
        __threadfence();
        unsigned old = atomicAdd(&g_ctr, 1u);
        s_last = (old == 575u);
    }
    __syncthreads();

    if (s_last) {
        __threadfence();
        float v = 0.f;
#pragma unroll
        for (int i = 0; i < 3; i++) {
            int idx = threadIdx.x + i * 256;
            if (idx < 576) v += g_part[idx];
        }
        __shared__ float rr[256];
        rr[threadIdx.x] = v;
        __syncthreads();
#pragma unroll
        for (int s = 128; s > 0; s >>= 1) {
            if (threadIdx.x < s) rr[threadIdx.x] += rr[threadIdx.x + s];
            __syncthreads();
        }
        if (threadIdx.x == 0) {
            out[0] = rr[0] * (1.0f / 4608.0f);
            g_ctr = 0u;
        }
    }
}

// ---------------- launch ----------------
extern "C" void kernel_launch(void* const* d_in, const int* in_sizes, int n_in,
                              void* d_out, int out_size) {
    const float* img1 = (const float*)d_in[0];
    const float* img2 = (const float*)d_in[1];
    const float* rel  = (const float*)d_in[2];
    const float* grid = (const float*)d_in[3];

    cudaFuncSetAttribute(k_main, cudaFuncAttributeMaxDynamicSharedMemorySize,
                         SM_TOT * (int)sizeof(float));

    k_prep<<<dim3(72, 4, 4), dim3(32, 8)>>>(img1, img2);
    k_gridsample<<<dim3(288, 2), 256>>>(grid);
    k_main<<<dim3(72, 2, 2), 256, SM_TOT * (int)sizeof(float)>>>();
    k_fin<<<576, 256>>>(rel, (float*)d_out);
}

// round 16
// speedup vs baseline: 1.1331x; 1.0222x over previous
#include <cuda_runtime.h>
#include <cuda_fp16.h>
#include <math.h>
#include <stdint.h>

#define BZ 2
#define CC 128
#define NN 2304
#define WIMG 48
#define ROWS 32         // n-rows per block
#define MC 128          // m-chunk width
#define NCH 9           // chunks per m-half (9*128 = 1152)
#define MHALF 1152
#define BPAD 68         // u32 row stride staged A/B (mod 32 == 4 -> frag reads conflict-free)
#define SSTR 129        // Ss row stride floats (mod 32 == 1 -> binning reads conflict-free)

// ---------------- scratch ----------------
__device__ __half g_Th[BZ * NN * CC];               // img2 -> [b][p][c] half
__device__ __half g_Dh[BZ * NN * CC];               // sampled db [b][n][c] half
__device__ float g_histP[(size_t)BZ * 2 * NN * 50]; // per-mhalf hists [b][mh][n][slot]
__device__ float g_part[576];
__device__ unsigned g_ctr = 0;

// ---------------- kernel 1: img2 transpose + cvt half (coalesced half2 stores) ----
__global__ void k_prep(const float* __restrict__ img2) {
    __shared__ float tile[64][33];
    int b = blockIdx.z;
    const float* in = img2 + (size_t)b * CC * NN;
    __half* out     = g_Th + (size_t)b * NN * CC;

    int p0 = blockIdx.x * 32;
    int c0 = blockIdx.y * 64;
    int tx = threadIdx.x, ty = threadIdx.y;    // (32, 8)

#pragma unroll
    for (int i = 0; i < 8; i++) {
        int cc = ty + 8 * i;
        tile[cc][tx] = in[(size_t)(c0 + cc) * NN + p0 + tx];
    }
    __syncthreads();
#pragma unroll
    for (int i2 = 0; i2 < 4; i2++) {
        int p = ty + 8 * i2;
        __half2 h = __floats2half2_rn(tile[2 * tx][p], tile[2 * tx + 1][p]);
        *(__half2*)(out + (size_t)(p0 + p) * CC + c0 + 2 * tx) = h;
    }
}

// ---------------- kernel 2: grid_sample ----------------
__global__ void k_gridsample(const float* __restrict__ grid) {
    int w    = threadIdx.x >> 5;
    int lane = threadIdx.x & 31;
    int n = blockIdx.x * 8 + w;
    int b = blockIdx.y;

    float gx = grid[((size_t)b * NN + n) * 2 + 0];
    float gy = grid[((size_t)b * NN + n) * 2 + 1];
    float ix = fmaf(gx, 24.0f, 23.5f);
    float iy = fmaf(gy, 24.0f, 23.5f);
    float x0f = floorf(ix), y0f = floorf(iy);
    float wx = ix - x0f, wy = iy - y0f;
    int x0 = (int)x0f, y0 = (int)y0f;
    int x1 = x0 + 1,  y1 = y0 + 1;

    bool vx0 = (x0 >= 0) & (x0 < WIMG);
    bool vx1 = (x1 >= 0) & (x1 < WIMG);
    bool vy0 = (y0 >= 0) & (y0 < WIMG);
    bool vy1 = (y1 >= 0) & (y1 < WIMG);

    float w00 = (vx0 & vy0) ? (1.f - wx) * (1.f - wy) : 0.f;
    float w10 = (vx1 & vy0) ? wx * (1.f - wy)         : 0.f;
    float w01 = (vx0 & vy1) ? (1.f - wx) * wy         : 0.f;
    float w11 = (vx1 & vy1) ? wx * wy                 : 0.f;

    int cx0 = min(max(x0, 0), WIMG - 1), cx1 = min(max(x1, 0), WIMG - 1);
    int cy0 = min(max(y0, 0), WIMG - 1), cy1 = min(max(y1, 0), WIMG - 1);

    const __half* T = g_Th + (size_t)b * NN * CC;
    int p00 = cy0 * WIMG + cx0, p10 = cy0 * WIMG + cx1;
    int p01 = cy1 * WIMG + cx0, p11 = cy1 * WIMG + cx1;

    uint2 v00 = ((const uint2*)(T + (size_t)p00 * CC))[lane];
    uint2 v10 = ((const uint2*)(T + (size_t)p10 * CC))[lane];
    uint2 v01 = ((const uint2*)(T + (size_t)p01 * CC))[lane];
    uint2 v11 = ((const uint2*)(T + (size_t)p11 * CC))[lane];

    float r[4];
#pragma unroll
    for (int h = 0; h < 2; h++) {
        float2 f00 = __half22float2(((__half2*)&v00)[h]);
        float2 f10 = __half22float2(((__half2*)&v10)[h]);
        float2 f01 = __half22float2(((__half2*)&v01)[h]);
        float2 f11 = __half22float2(((__half2*)&v11)[h]);
        r[2 * h + 0] = w00 * f00.x + w10 * f10.x + w01 * f01.x + w11 * f11.x;
        r[2 * h + 1] = w00 * f00.y + w10 * f10.y + w01 * f01.y + w11 * f11.y;
    }
    uint2 o;
    ((__half2*)&o)[0] = __floats2half2_rn(r[0], r[1]);
    ((__half2*)&o)[1] = __floats2half2_rn(r[2], r[3]);
    ((uint2*)(g_Dh + ((size_t)b * NN + n) * CC))[lane] = o;
}

// ---------------- fp16 MMA ----------------
__device__ __forceinline__ void mma_f16(float* d, const uint32_t* a, const uint32_t* bb) {
    asm volatile(
        "mma.sync.aligned.m16n8k16.row.col.f32.f16.f16.f32 "
        "{%0,%1,%2,%3}, {%4,%5,%6,%7}, {%8,%9}, {%0,%1,%2,%3};"
        : "+f"(d[0]), "+f"(d[1]), "+f"(d[2]), "+f"(d[3])
        : "r"(a[0]), "r"(a[1]), "r"(a[2]), "r"(a[3]), "r"(bb[0]), "r"(bb[1]));
}

// ---------------- kernel 3: GEMM + binning over one m-half (288 blocks, occ 2) ----
#define SM_SS   0                          // 32*129 = 4128
#define SM_HN   (SM_SS + ROWS * SSTR)      // 26*256 = 6656
#define SM_HR   (SM_HN + 26 * 256)         // 6656
#define SM_A    (SM_HR + 26 * 256)         // 32*68 u32 = 2176
#define SM_B    (SM_A + ROWS * BPAD)       // 128*68 u32 = 8704
#define SM_TOT  (SM_B + MC * BPAD)         // 28320 floats = 113280 B

__global__ void __launch_bounds__(256, 2) k_main(const float* __restrict__ img1) {
    extern __shared__ float smf[];
    float*    Ss  = smf + SM_SS;
    float*    hN  = smf + SM_HN;
    float*    hR  = smf + SM_HR;
    uint32_t* As2 = (uint32_t*)(smf + SM_A);
    uint32_t* Bs2 = (uint32_t*)(smf + SM_B);

    const int t  = threadIdx.x;
    const int w  = t >> 5;
    const int ln = t & 31;
    const int g  = ln >> 2;
    const int tg = ln & 3;
    const int nt = blockIdx.x;
    const int mh = blockIdx.y;
    const int b  = blockIdx.z;
    const int n0 = nt * ROWS;
    const int mbase = mh * MHALF;

    // zero private hist columns
#pragma unroll
    for (int c = 0; c < 26; c++) { hN[c * 256 + t] = 0.f; hR[c * 256 + t] = 0.f; }

    // stage A directly from img1 [c][n] fp32: warp w covers c = w*16..w*16+15
    // lane reads 32 consecutive n (128B coalesced), packs half2, STS.32
    const float* Q1 = img1 + (size_t)b * CC * NN + n0;
#pragma unroll
    for (int i = 0; i < 8; i++) {
        int c = w * 16 + 2 * i;
        float v0 = Q1[(size_t)c * NN + ln];
        float v1 = Q1[(size_t)(c + 1) * NN + ln];
        __half2 h = __floats2half2_rn(v0, v1);
        As2[ln * BPAD + w * 8 + i] = *(uint32_t*)&h;
    }

    // binning identities: lane = row
    const int ng = n0 + ln;
    const int rn = ng / WIMG;
    const int cn = ng - rn * WIMG;

    const __half* Dh = g_Dh + (size_t)(b * NN + mbase) * CC;

    // preload B chunk 0: 2048 uint4, 8 per thread
#pragma unroll
    for (int i = 0; i < 8; i++) {
        int idx = t + i * 256;
        int m = idx >> 4, c4 = idx & 15;
        uint4 v = ((const uint4*)(Dh + (size_t)m * CC))[c4];
        *(uint4*)&Bs2[m * BPAD + c4 * 4] = v;
    }
    __syncthreads();

    // ---- cache ALL A fragments in registers (A is chunk-invariant) ----
    uint32_t afr[8][2][4];
#pragma unroll
    for (int kk = 0; kk < 8; kk++) {
        int kb = kk * 8 + tg;
#pragma unroll
        for (int rt = 0; rt < 2; rt++) {
            int nb = rt * 16 + g;
            afr[kk][rt][0] = As2[nb * BPAD + kb];
            afr[kk][rt][1] = As2[(nb + 8) * BPAD + kb];
            afr[kk][rt][2] = As2[nb * BPAD + kb + 4];
            afr[kk][rt][3] = As2[(nb + 8) * BPAD + kb + 4];
        }
    }

    for (int mc = 0; mc < NCH; mc++) {
        const int m0 = mc * MC;

        // ---- GEMM: warp w covers m-cols [w*16, w*16+16) ----
        float acc[2][2][4];
#pragma unroll
        for (int i = 0; i < 2; i++)
#pragma unroll
            for (int j = 0; j < 2; j++)
#pragma unroll
                for (int k = 0; k < 4; k++) acc[i][j][k] = 0.f;

#pragma unroll
        for (int kk = 0; kk < 8; kk++) {
            int kb = kk * 8 + tg;
#pragma unroll
            for (int ct = 0; ct < 2; ct++) {
                int mb = w * 16 + ct * 8 + g;
                uint32_t bf[2];
                bf[0] = Bs2[mb * BPAD + kb];
                bf[1] = Bs2[mb * BPAD + kb + 4];
#pragma unroll
                for (int rt = 0; rt < 2; rt++)
                    mma_f16(acc[rt][ct], afr[kk][rt], bf);
            }
        }

        // fragments -> Ss (scalar stores: SSTR odd)
#pragma unroll
        for (int rt = 0; rt < 2; rt++) {
            int row = rt * 16 + g;
#pragma unroll
            for (int ct = 0; ct < 2; ct++) {
                int col = w * 16 + ct * 8 + tg * 2;
                Ss[row * SSTR + col]           = acc[rt][ct][0];
                Ss[row * SSTR + col + 1]       = acc[rt][ct][1];
                Ss[(row + 8) * SSTR + col]     = acc[rt][ct][2];
                Ss[(row + 8) * SSTR + col + 1] = acc[rt][ct][3];
            }
        }
        __syncthreads();

        // ---- stage next B chunk (overlaps binning) ----
        if (mc + 1 < NCH) {
            const __half* Dn = Dh + (size_t)(m0 + MC) * CC;
#pragma unroll
            for (int i = 0; i < 8; i++) {
                int idx = t + i * 256;
                int m = idx >> 4, c4 = idx & 15;
                uint4 v = ((const uint4*)(Dn + (size_t)m * CC))[c4];
                *(uint4*)&Bs2[m * BPAD + c4 * 4] = v;
            }
        }

        // ---- binning: row = lane, warp w covers m = w + 8j ----
        {
            float* hNc = hN + t;
            float* hRc = hR + t;
            const int mgb = mbase + m0 + w;
#pragma unroll
            for (int j = 0; j < 16; j++) {
                int ml = w + 8 * j;
                float s = Ss[ln * SSTR + ml];
                int mg = mgb + 8 * j;
                int rm = mg / WIMG;
                int cm = mg - rm * WIMG;
                bool lab = (abs(rm - rn) <= 4) && (abs(cm - cn) <= 4);
                float tq = fmaf(s, -12.f, 12.f);
                tq = fminf(fmaxf(tq, 0.f), 24.f);
                float cf = floorf(tq);
                int c0 = (int)cf;
                float whi = tq - cf;
                float wlo = 1.f - whi;
                hNc[c0 * 256]       += wlo;
                hNc[c0 * 256 + 256] += whi;
                if (__any_sync(0xffffffffu, lab)) {
                    if (lab) {
                        hRc[c0 * 256]       += wlo;
                        hRc[c0 * 256 + 256] += whi;
                    }
                }
            }
        }
        __syncthreads();
    }

    // ---- flush: 50 slots x 32 rows -> g_histP[b][mh][n][slot] (row-major) ----
    float* outp = g_histP + ((size_t)((b * 2 + mh) * NN + n0)) * 50;
#pragma unroll
    for (int kk = 0; kk < 7; kk++) {
        int idx = t + kk * 256;            // 0..1599 used
        if (idx < 1600) {
            int s50 = idx >> 5;            // 0..49
            int r   = idx & 31;
            float* hh = (s50 < 25) ? (hN + s50 * 256) : (hR + (s50 - 25) * 256);
            float v = 0.f;
#pragma unroll
            for (int u = 0; u < 8; u++) v += hh[u * 32 + r];
            outp[(size_t)r * 50 + s50] = v;
        }
    }
}

// ---------------- kernel 4: AP + loss, warp-per-row, coalesced row-major hists ----
__global__ void __launch_bounds__(256) k_fin(const float* __restrict__ rel,
                                             float* __restrict__ out) {
    const int wib  = threadIdx.x >> 5;
    const int lane = threadIdx.x & 31;
    const int row  = blockIdx.x * 8 + wib;     // 0..4607
    const int b = row / NN;
    const int n = row - b * NN;

    const float* P0 = g_histP + ((size_t)((b * 2 + 0) * NN + n)) * 50;
    const float* P1 = g_histP + ((size_t)((b * 2 + 1) * NN + n)) * 50;

    float nb = 0.f, rv = 0.f;
    if (lane < 25) {
        nb = P0[lane]      + P1[lane];
        rv = P0[25 + lane] + P1[25 + lane];
    }

    // inclusive scans over lanes (bins)
    float cumn = nb, cumr = rv;
#pragma unroll
    for (int o = 1; o < 32; o <<= 1) {
        float a = __shfl_up_sync(0xffffffffu, cumn, o);
        float c = __shfl_up_sync(0xffffffffu, cumr, o);
        if (lane >= o) { cumn += a; cumr += c; }
    }
    float prec = cumr / (1e-16f + cumn);
    float term = prec * rv;                    // lanes >= 25 contribute 0
    float sr   = rv;
#pragma unroll
    for (int o = 16; o > 0; o >>= 1) {
        term += __shfl_down_sync(0xffffffffu, term, o);
        sr   += __shfl_down_sync(0xffffffffu, sr, o);
    }

    __shared__ float red[8];
    if (lane == 0) {
        float ap = term / sr;
        float rl = rel[(size_t)b * NN + n];
        red[wib] = 1.f - (ap * rl + 0.5f * (1.f - rl));
    }
    __syncthreads();

    __shared__ bool s_last;
    if (threadIdx.x == 0) {
        float bs = 0.f;
#pragma unroll
        for (int i = 0; i < 8; i++) bs += red[i];
        g_part[blockIdx.x] = bs;
        __threadfence();
        unsigned old = atomicAdd(&g_ctr, 1u);
        s_last = (old == 575u);
    }
    __syncthreads();

    if (s_last) {
        __threadfence();
        float v = 0.f;
#pragma unroll
        for (int i = 0; i < 3; i++) {
            int idx = threadIdx.x + i * 256;
            if (idx < 576) v += g_part[idx];
        }
        __shared__ float rr[256];
        rr[threadIdx.x] = v;
        __syncthreads();
#pragma unroll
        for (int s = 128; s > 0; s >>= 1) {
            if (threadIdx.x < s) rr[threadIdx.x] += rr[threadIdx.x + s];
            __syncthreads();
        }
        if (threadIdx.x == 0) {
            out[0] = rr[0] * (1.0f / 4608.0f);
            g_ctr = 0u;
        }
    }
}

// ---------------- launch ----------------
extern "C" void kernel_launch(void* const* d_in, const int* in_sizes, int n_in,
                              void* d_out, int out_size) {
    const float* img1 = (const float*)d_in[0];
    const float* img2 = (const float*)d_in[1];
    const float* rel  = (const float*)d_in[2];
    const float* grid = (const float*)d_in[3];

    cudaFuncSetAttribute(k_main, cudaFuncAttributeMaxDynamicSharedMemorySize,
                         SM_TOT * (int)sizeof(float));

    k_prep<<<dim3(72, 2, 2), dim3(32, 8)>>>(img2);
    k_gridsample<<<dim3(288, 2), 256>>>(grid);
    k_main<<<dim3(72, 2, 2), 256, SM_TOT * (int)sizeof(float)>>>(img1);
    k_fin<<<576, 256>>>(rel, (float*)d_out);
}